// round 1
// baseline (speedup 1.0000x reference)
#include <cuda_runtime.h>
#include <math.h>

// Problem constants
#define Bv 4
#define Nv 8192
#define Sv 12
#define Lv 5
#define Ev 131072
#define CAP 128
#define BN (Bv*Nv)        // 32768 sequences
#define FSZ (Bv*Nv*Sv)    // 393216 floats per feature map

// ---------------- scratch (static __device__ allowed; no runtime alloc) ----
__device__ float g_xp[FSZ];
__device__ float g_c1[FSZ];
__device__ float g_c2[FSZ];
__device__ float g_c4[FSZ];
__device__ float g_c5[FSZ];
__device__ float g_acc[FSZ];
__device__ float g_p[Nv];
__device__ float g_q[Nv];
__device__ int   g_fill[Nv];
__device__ int   g_ucnt[Nv];
__device__ int   g_ci[Nv*CAP];
__device__ float g_cv[Nv*CAP];
__device__ int   g_uci[Nv*CAP];
__device__ float g_ucv[Nv*CAP];
__device__ float g_esum[Bv*Sv];

__device__ __forceinline__ float* bufsel(int id) {
    switch (id) {
        case 0: return g_xp;
        case 1: return g_c1;
        case 2: return g_c2;
        case 3: return g_c4;
        default: return g_c5;
    }
}

__device__ __forceinline__ float sigmf(float x) {
    return 1.0f / (1.0f + __expf(-x));
}
__device__ __forceinline__ float tanhfast(float x) {
    // safe at large |x|: exp->inf gives 1-0=1 ; exp->0 gives 1-2=-1
    return 1.0f - 2.0f / (__expf(2.0f * x) + 1.0f);
}

// ---------------- kernels --------------------------------------------------

// x (B,S,N) -> g_xp (B,N,S)
__global__ void k_transpose(const float* __restrict__ x) {
    int idx = blockIdx.x * blockDim.x + threadIdx.x;
    if (idx >= FSZ) return;
    int s = idx % Sv;
    int r = idx / Sv;
    int n = r % Nv;
    int b = r / Nv;
    g_xp[idx] = x[(b * Sv + s) * Nv + n];
}

__global__ void k_zero() {
    int idx = blockIdx.x * blockDim.x + threadIdx.x;
    if (idx < FSZ) g_acc[idx] = 0.0f;
    if (idx < Nv) { g_fill[idx] = 0; g_ucnt[idx] = 0; }
    if (idx < Bv * Sv) g_esum[idx] = 0.0f;
}

// p[i] = X0[i,:] . (W @ a[:S]) ; q[i] = X0[i,:] . (W @ a[S:])
__global__ void k_pq(int xid, const float* __restrict__ W, const float* __restrict__ a) {
    __shared__ float wa[Sv], wb[Sv];
    int t = threadIdx.x;
    if (t < Sv) {
        float s1 = 0.f, s2 = 0.f;
        #pragma unroll
        for (int u = 0; u < Sv; u++) {
            float w = W[t * Sv + u];
            s1 += w * a[u];
            s2 += w * a[Sv + u];
        }
        wa[t] = s1; wb[t] = s2;
    }
    __syncthreads();
    int i = blockIdx.x * blockDim.x + threadIdx.x;
    if (i >= Nv) return;
    const float* X0 = bufsel(xid);   // batch 0 rows
    float p = 0.f, q = 0.f;
    #pragma unroll
    for (int s = 0; s < Sv; s++) {
        float v = X0[i * Sv + s];
        p += v * wa[s];
        q += v * wb[s];
    }
    g_p[i] = p; g_q[i] = q;
}

// per-edge score, bucketed by destination column
__global__ void k_edge(const int* __restrict__ ed, const float* __restrict__ lw,
                       const float* __restrict__ lb) {
    int k = blockIdx.x * blockDim.x + threadIdx.x;
    if (k >= Ev) return;
    int i = ed[k];
    int j = ed[Ev + k];
    float e = g_p[i] + g_q[j];
    e = (e > 0.f) ? e : 0.2f * e;              // leaky_relu slope 0.2
    float val = e * lw[0] + lb[0];
    int pos = atomicAdd(&g_fill[j], 1);
    if (pos < CAP) {
        g_ci[j * CAP + pos] = i;
        g_cv[j * CAP + pos] = val;
    }
}

// per-column: dedup duplicate (i,j) edges (add), softmax over column
__global__ void k_col(int xid) {
    int j = blockIdx.x * blockDim.x + threadIdx.x;
    if (j >= Nv) return;
    int k = min(g_fill[j], CAP);
    if (k == 0) {
        // empty column -> uniform softmax 1/N over all rows: rank-1 correction
        const float* X = bufsel(xid);
        for (int b = 0; b < Bv; b++)
            #pragma unroll
            for (int s = 0; s < Sv; s++)
                atomicAdd(&g_esum[b * Sv + s], X[(b * Nv + j) * Sv + s]);
        g_ucnt[j] = 0;
        return;
    }
    const int*   ci  = g_ci  + j * CAP;
    const float* cv  = g_cv  + j * CAP;
    int*         uci = g_uci + j * CAP;
    float*       ucv = g_ucv + j * CAP;
    int u = 0;
    float m = -1e30f;
    for (int t = 0; t < k; t++) {
        int i = ci[t];
        bool lead = true;
        for (int t2 = 0; t2 < t; t2++)
            if (ci[t2] == i) { lead = false; break; }
        if (!lead) continue;
        float s = cv[t];
        for (int t2 = t + 1; t2 < k; t2++)
            if (ci[t2] == i) s += cv[t2];
        uci[u] = i; ucv[u] = s; u++;
        m = fmaxf(m, s);
    }
    float den = 0.f;
    for (int t = 0; t < u; t++) {
        float e = __expf(ucv[t] - m);
        ucv[t] = e;
        den += e;
    }
    float inv = 1.0f / den;
    for (int t = 0; t < u; t++) ucv[t] *= inv;
    g_ucnt[j] = u;
}

// acc[b,i,:] += w * Xin[b,j,:] over sparse softmax entries
__global__ void k_spmm(int xid) {
    int tid = blockIdx.x * blockDim.x + threadIdx.x;
    if (tid >= Nv * Bv) return;
    int j = tid >> 2;
    int b = tid & 3;
    int u = g_ucnt[j];
    if (u == 0) return;
    const float* X = bufsel(xid);
    float xv[Sv];
    #pragma unroll
    for (int s = 0; s < Sv; s++) xv[s] = X[(b * Nv + j) * Sv + s];
    const int*   uci = g_uci + j * CAP;
    const float* ucv = g_ucv + j * CAP;
    for (int t = 0; t < u; t++) {
        int   i = uci[t];
        float w = ucv[t];
        float* dst = g_acc + (b * Nv + i) * Sv;
        #pragma unroll
        for (int s = 0; s < Sv; s++) atomicAdd(dst + s, w * xv[s]);
    }
}

// GCN: leaky_relu(z @ gcnW^T + gcnb, 0.01), with empty-column rank-1 add
__global__ void k_gcn(int outid, const float* __restrict__ gcnW,
                      const float* __restrict__ gcnb) {
    int tid = blockIdx.x * blockDim.x + threadIdx.x;
    if (tid >= BN) return;
    float* Xout = bufsel(outid);
    int b = tid / Nv;
    float z[Sv];
    #pragma unroll
    for (int s = 0; s < Sv; s++)
        z[s] = g_acc[tid * Sv + s] + g_esum[b * Sv + s] * (1.0f / (float)Nv);
    #pragma unroll
    for (int s = 0; s < Sv; s++) {
        float y = gcnb[s];
        #pragma unroll
        for (int t = 0; t < Sv; t++) y += z[t] * gcnW[s * Sv + t];
        Xout[tid * Sv + s] = (y > 0.f) ? y : 0.01f * y;
    }
}

// fused 2-layer LSTM + temporal attention head; one thread per sequence
__global__ void __launch_bounds__(128)
k_lstm(const float* __restrict__ Wih0, const float* __restrict__ Whh0,
       const float* __restrict__ bih0, const float* __restrict__ bhh0,
       const float* __restrict__ Wih1, const float* __restrict__ Whh1,
       const float* __restrict__ bih1, const float* __restrict__ bhh1,
       const float* __restrict__ fc1W, const float* __restrict__ fc1b,
       const float* __restrict__ fc2W, const float* __restrict__ fc2b,
       const float* __restrict__ fc3W, const float* __restrict__ fc3b,
       float* __restrict__ out, int out_size) {
    __shared__ float sWih0[100], sWhh0[100], sB0[20];
    __shared__ float sWih1[100], sWhh1[100], sB1[20];
    __shared__ float sF1[176], sF1b[16], sF2[80], sF2b[5], sF3[21], sF3b;
    int t = threadIdx.x;
    for (int i = t; i < 100; i += blockDim.x) {
        sWih0[i] = Wih0[i]; sWhh0[i] = Whh0[i];
        sWih1[i] = Wih1[i]; sWhh1[i] = Whh1[i];
    }
    for (int i = t; i < 20; i += blockDim.x) {
        sB0[i] = bih0[i] + bhh0[i];
        sB1[i] = bih1[i] + bhh1[i];
    }
    for (int i = t; i < 176; i += blockDim.x) sF1[i] = fc1W[i];
    for (int i = t; i < 80;  i += blockDim.x) sF2[i] = fc2W[i];
    for (int i = t; i < 21;  i += blockDim.x) sF3[i] = fc3W[i];
    for (int i = t; i < 16;  i += blockDim.x) sF1b[i] = fc1b[i];
    for (int i = t; i < 5;   i += blockDim.x) sF2b[i] = fc2b[i];
    if (t == 0) sF3b = fc3b[0];
    __syncthreads();

    int seq = blockIdx.x * blockDim.x + threadIdx.x;
    if (seq >= BN) return;
    int base = seq * Sv;

    float h0[Lv], c0[Lv], h1[Lv], c1l[Lv];
    #pragma unroll
    for (int l = 0; l < Lv; l++) { h0[l]=0.f; c0[l]=0.f; h1[l]=0.f; c1l[l]=0.f; }

    float h2s[Sv][Lv];   // layer-2 outputs per timestep

    #pragma unroll 1
    for (int tt = 0; tt < Sv; tt++) {
        float xv[Lv];
        xv[0] = g_xp[base + tt];
        xv[1] = g_c1[base + tt];
        xv[2] = g_c2[base + tt];
        xv[3] = g_c4[base + tt];
        xv[4] = g_c5[base + tt];

        // layer 0
        float z[20];
        #pragma unroll
        for (int g = 0; g < 20; g++) {
            float zz = sB0[g];
            #pragma unroll
            for (int l = 0; l < Lv; l++)
                zz += sWih0[g * Lv + l] * xv[l] + sWhh0[g * Lv + l] * h0[l];
            z[g] = zz;
        }
        #pragma unroll
        for (int l = 0; l < Lv; l++) {
            float ig = sigmf(z[l]);
            float fg = sigmf(z[5 + l]);
            float gg = tanhfast(z[10 + l]);
            float og = sigmf(z[15 + l]);
            c0[l] = fg * c0[l] + ig * gg;
            h0[l] = og * tanhfast(c0[l]);
        }
        // layer 1 (input = h0)
        #pragma unroll
        for (int g = 0; g < 20; g++) {
            float zz = sB1[g];
            #pragma unroll
            for (int l = 0; l < Lv; l++)
                zz += sWih1[g * Lv + l] * h0[l] + sWhh1[g * Lv + l] * h1[l];
            z[g] = zz;
        }
        #pragma unroll
        for (int l = 0; l < Lv; l++) {
            float ig = sigmf(z[l]);
            float fg = sigmf(z[5 + l]);
            float gg = tanhfast(z[10 + l]);
            float og = sigmf(z[15 + l]);
            c1l[l] = fg * c1l[l] + ig * gg;
            h1[l] = og * tanhfast(c1l[l]);
            h2s[tt][l] = h1[l];
        }
    }

    // ---- TPA head ----
    float Hc[Lv][16];
    #pragma unroll
    for (int l = 0; l < Lv; l++) {
        #pragma unroll
        for (int k = 0; k < 16; k++) {
            float acc = sF1b[k];
            #pragma unroll 1
            for (int tt = 0; tt < Sv - 1; tt++)
                acc += h2s[tt][l] * sF1[k * (Sv - 1) + tt];
            Hc[l][k] = acc;
        }
    }
    float ht[Lv];
    #pragma unroll
    for (int m = 0; m < Lv; m++) ht[m] = h2s[Sv - 1][m];

    float av[Lv];
    #pragma unroll
    for (int l = 0; l < Lv; l++) {
        float s = 0.f;
        #pragma unroll
        for (int m = 0; m < Lv; m++) {
            float hn = sF2b[m];
            #pragma unroll
            for (int k = 0; k < 16; k++) hn += Hc[l][k] * sF2[m * 16 + k];
            s += hn * ht[m];
        }
        av[l] = sigmf(s);
    }

    float y = sF3b;
    #pragma unroll
    for (int k = 0; k < 16; k++) {
        float vt = 0.f;
        #pragma unroll
        for (int l = 0; l < Lv; l++) vt += av[l] * Hc[l][k];
        y += vt * sF3[k];
    }
    #pragma unroll
    for (int m = 0; m < Lv; m++) y += ht[m] * sF3[16 + m];

    out[seq] = y;                                    // TPA_y flat (b*N+n)
    if (BN + seq * Lv + (Lv - 1) < out_size) {
        #pragma unroll
        for (int l = 0; l < Lv; l++)
            out[BN + seq * Lv + l] = av[l];          // a flat
    }
}

// ---------------- launcher -------------------------------------------------
extern "C" void kernel_launch(void* const* d_in, const int* in_sizes, int n_in,
                              void* d_out, int out_size) {
    const float* x    = (const float*)d_in[0];
    const int*   e1   = (const int*)  d_in[1];
    const int*   e2   = (const int*)  d_in[2];
    const float* g1W  = (const float*)d_in[3];
    const float* g1a  = (const float*)d_in[4];
    const float* g1lw = (const float*)d_in[5];
    const float* g1lb = (const float*)d_in[6];
    const float* g2W  = (const float*)d_in[7];
    const float* g2a  = (const float*)d_in[8];
    const float* g2lw = (const float*)d_in[9];
    const float* g2lb = (const float*)d_in[10];
    const float* gcnW = (const float*)d_in[11];
    const float* gcnb = (const float*)d_in[12];
    const float* Wih0 = (const float*)d_in[13];
    const float* Whh0 = (const float*)d_in[14];
    const float* bih0 = (const float*)d_in[15];
    const float* bhh0 = (const float*)d_in[16];
    const float* Wih1 = (const float*)d_in[17];
    const float* Whh1 = (const float*)d_in[18];
    const float* bih1 = (const float*)d_in[19];
    const float* bhh1 = (const float*)d_in[20];
    const float* fc1W = (const float*)d_in[21];
    const float* fc1b = (const float*)d_in[22];
    const float* fc2W = (const float*)d_in[23];
    const float* fc2b = (const float*)d_in[24];
    const float* fc3W = (const float*)d_in[25];
    const float* fc3b = (const float*)d_in[26];

    const int TB = 256;
    k_transpose<<<(FSZ + TB - 1) / TB, TB>>>(x);

    struct StageArgs {
        int xin, xout;
        const int* ed;
        const float *W, *a, *lw, *lb;
    };
    StageArgs stages[4] = {
        {0, 1, e1, g1W, g1a, g1lw, g1lb},
        {1, 2, e1, g1W, g1a, g1lw, g1lb},
        {0, 3, e2, g2W, g2a, g2lw, g2lb},
        {3, 4, e2, g2W, g2a, g2lw, g2lb},
    };
    for (int st = 0; st < 4; st++) {
        StageArgs& A = stages[st];
        k_zero<<<(FSZ + TB - 1) / TB, TB>>>();
        k_pq<<<(Nv + TB - 1) / TB, TB>>>(A.xin, A.W, A.a);
        k_edge<<<(Ev + TB - 1) / TB, TB>>>(A.ed, A.lw, A.lb);
        k_col<<<(Nv + TB - 1) / TB, TB>>>(A.xin);
        k_spmm<<<(Nv * Bv + TB - 1) / TB, TB>>>(A.xin);
        k_gcn<<<(BN + TB - 1) / TB, TB>>>(A.xout, gcnW, gcnb);
    }

    k_lstm<<<(BN + 127) / 128, 128>>>(Wih0, Whh0, bih0, bhh0,
                                      Wih1, Whh1, bih1, bhh1,
                                      fc1W, fc1b, fc2W, fc2b, fc3W, fc3b,
                                      (float*)d_out, out_size);
}

// round 3
// speedup vs baseline: 1.3548x; 1.3548x over previous
#include <cuda_runtime.h>
#include <math.h>

// Problem constants
#define Bv 4
#define Nv 8192
#define Sv 12
#define Lv 5
#define Ev 131072
#define CAP 128
#define BN (Bv*Nv)        // 32768 sequences
#define FSZ (Bv*Nv*Sv)    // floats per feature map

// ---------------- scratch ----------------
// Feature maps, A-layout (bn, s) and B-layout (s, bn)
__device__ float g_xpA[FSZ], g_xpB[FSZ];
__device__ float g_c1A[FSZ], g_c1B[FSZ];
__device__ float g_c2A[FSZ], g_c2B[FSZ];
__device__ float g_c4A[FSZ], g_c4B[FSZ];
__device__ float g_c5A[FSZ], g_c5B[FSZ];

// Graph structure, per edge list (2 lists)
__device__ int g_fill [2][Nv];        // column bucket fill
__device__ int g_ci   [2][Nv*CAP];    // raw bucketed source indices
__device__ int g_ucnt [2][Nv];        // unique count per column
__device__ int g_uci  [2][Nv*CAP];    // unique source index
__device__ int g_mult [2][Nv*CAP];    // multiplicity
__device__ int g_rfill[2][Nv];        // row bucket fill
__device__ int g_reid [2][Nv*CAP];    // row -> entry id (j*CAP + t)

// Per-stage values
__device__ float g_p[Nv];
__device__ float g_q[Nv];
__device__ float g_w[Nv*CAP];         // softmax weights, indexed j*CAP+t
__device__ float g_esum[Bv*Sv];       // empty-column rank-1 correction

__device__ __forceinline__ const float* bufA(int id) {
    switch (id) { case 0: return g_xpA; case 1: return g_c1A; case 2: return g_c2A;
                  case 3: return g_c4A; default: return g_c5A; }
}
__device__ __forceinline__ float* bufAw(int id) {
    switch (id) { case 0: return g_xpA; case 1: return g_c1A; case 2: return g_c2A;
                  case 3: return g_c4A; default: return g_c5A; }
}
__device__ __forceinline__ float* bufBw(int id) {
    switch (id) { case 0: return g_xpB; case 1: return g_c1B; case 2: return g_c2B;
                  case 3: return g_c4B; default: return g_c5B; }
}

__device__ __forceinline__ float sigmf(float x) { return 1.0f / (1.0f + __expf(-x)); }
__device__ __forceinline__ float tanhfast(float x) {
    return 1.0f - 2.0f / (__expf(2.0f * x) + 1.0f);
}

// ---------------- structure precompute (once per edge list) ----------------

__global__ void k_zero_struct() {
    int idx = blockIdx.x * blockDim.x + threadIdx.x;
    if (idx < Nv) {
        g_fill[0][idx] = 0; g_fill[1][idx] = 0;
        g_rfill[0][idx] = 0; g_rfill[1][idx] = 0;
    }
}

// x (B,S,N) -> A-layout (b,n,s) and B-layout (s,b,n)
__global__ void k_transpose(const float* __restrict__ x) {
    int idx = blockIdx.x * blockDim.x + threadIdx.x;   // (b, s, n) order: coalesced read
    if (idx >= FSZ) return;
    int n = idx % Nv;
    int r = idx / Nv;
    int s = r % Sv;
    int b = r / Sv;
    float v = x[idx];
    g_xpA[(b * Nv + n) * Sv + s] = v;
    g_xpB[s * BN + b * Nv + n]   = v;
}

__global__ void k_bucket(const int* __restrict__ ed, int lid) {
    int k = blockIdx.x * blockDim.x + threadIdx.x;
    if (k >= Ev) return;
    int i = ed[k];
    int j = ed[Ev + k];
    int pos = atomicAdd(&g_fill[lid][j], 1);
    if (pos < CAP) g_ci[lid][j * CAP + pos] = i;
}

__global__ void k_dedup(int lid) {
    int j = blockIdx.x * blockDim.x + threadIdx.x;
    if (j >= Nv) return;
    int k = min(g_fill[lid][j], CAP);
    const int* ci = g_ci[lid] + j * CAP;
    int* uci = g_uci[lid] + j * CAP;
    int* mlt = g_mult[lid] + j * CAP;
    int u = 0;
    for (int t = 0; t < k; t++) {
        int i = ci[t];
        bool lead = true;
        for (int t2 = 0; t2 < t; t2++)
            if (ci[t2] == i) { lead = false; break; }
        if (!lead) continue;
        int m = 1;
        for (int t2 = t + 1; t2 < k; t2++)
            if (ci[t2] == i) m++;
        uci[u] = i; mlt[u] = m; u++;
    }
    g_ucnt[lid][j] = u;
}

__global__ void k_rowbuild(int lid) {
    int j = blockIdx.x * blockDim.x + threadIdx.x;
    if (j >= Nv) return;
    int u = g_ucnt[lid][j];
    const int* uci = g_uci[lid] + j * CAP;
    for (int t = 0; t < u; t++) {
        int i = uci[t];
        int pos = atomicAdd(&g_rfill[lid][i], 1);
        if (pos < CAP) g_reid[lid][i * CAP + pos] = j * CAP + t;
    }
}

// ---------------- per-stage kernels ----------------

// p[i] = X0[i,:].(W@a[:S]) ; q[i] = X0[i,:].(W@a[S:]); also zeros g_esum
__global__ void k_pq(int xid, const float* __restrict__ W, const float* __restrict__ a) {
    __shared__ float wa[Sv], wb[Sv];
    int t = threadIdx.x;
    if (t < Sv) {
        float s1 = 0.f, s2 = 0.f;
        #pragma unroll
        for (int u = 0; u < Sv; u++) {
            float w = W[t * Sv + u];
            s1 += w * a[u];
            s2 += w * a[Sv + u];
        }
        wa[t] = s1; wb[t] = s2;
    }
    __syncthreads();
    int i = blockIdx.x * blockDim.x + threadIdx.x;
    if (i < Bv * Sv) g_esum[i] = 0.0f;
    if (i >= Nv) return;
    const float* X0 = bufA(xid);
    float p = 0.f, q = 0.f;
    #pragma unroll
    for (int s = 0; s < Sv; s++) {
        float v = X0[i * Sv + s];
        p += v * wa[s];
        q += v * wb[s];
    }
    g_p[i] = p; g_q[i] = q;
}

// per-column softmax over unique entries; duplicate edges contribute mult*val
__global__ void k_colw(int lid, int xid, const float* __restrict__ lw,
                       const float* __restrict__ lb) {
    int j = blockIdx.x * blockDim.x + threadIdx.x;
    if (j >= Nv) return;
    int u = g_ucnt[lid][j];
    if (u == 0) {
        // empty column -> uniform 1/N over all rows: rank-1 correction
        const float* X = bufA(xid);
        for (int b = 0; b < Bv; b++)
            #pragma unroll
            for (int s = 0; s < Sv; s++)
                atomicAdd(&g_esum[b * Sv + s], X[(b * Nv + j) * Sv + s]);
        return;
    }
    const int* uci = g_uci[lid] + j * CAP;
    const int* mlt = g_mult[lid] + j * CAP;
    float* wv = g_w + j * CAP;
    float qj = g_q[j];
    float lwv = lw[0], lbv = lb[0];
    float m = -1e30f;
    for (int t = 0; t < u; t++) {
        float e = g_p[uci[t]] + qj;
        e = (e > 0.f) ? e : 0.2f * e;
        float val = (float)mlt[t] * (e * lwv + lbv);
        wv[t] = val;
        m = fmaxf(m, val);
    }
    float den = 0.f;
    for (int t = 0; t < u; t++) {
        float e = __expf(wv[t] - m);
        wv[t] = e;
        den += e;
    }
    float inv = 1.0f / den;
    for (int t = 0; t < u; t++) wv[t] *= inv;
}

// gather SpMM + fused GCN; no atomics. thread = b*Nv + i (i fastest)
__global__ void k_gathergcn(int lid, int xid, int outid,
                            const float* __restrict__ gcnW,
                            const float* __restrict__ gcnb) {
    __shared__ float sW[Sv * Sv], sb[Sv];
    int tt = threadIdx.x;
    if (tt < Sv * Sv) sW[tt] = gcnW[tt];
    if (tt < Sv) sb[tt] = gcnb[tt];
    __syncthreads();

    int tid = blockIdx.x * blockDim.x + threadIdx.x;
    if (tid >= BN) return;
    int i = tid & (Nv - 1);
    int b = tid >> 13;

    const float* X = bufA(xid);
    const int* reid = g_reid[lid] + i * CAP;
    int deg = min(g_rfill[lid][i], CAP);

    float z[Sv];
    #pragma unroll
    for (int s = 0; s < Sv; s++) z[s] = 0.f;

    for (int t = 0; t < deg; t++) {
        int eid = reid[t];
        float w = g_w[eid];
        int j = eid >> 7;   // CAP = 128
        const float4* xr = (const float4*)(X + (b * Nv + j) * Sv);
        float4 v0 = xr[0], v1 = xr[1], v2 = xr[2];
        z[0] += w * v0.x; z[1] += w * v0.y; z[2]  += w * v0.z; z[3]  += w * v0.w;
        z[4] += w * v1.x; z[5] += w * v1.y; z[6]  += w * v1.z; z[7]  += w * v1.w;
        z[8] += w * v2.x; z[9] += w * v2.y; z[10] += w * v2.z; z[11] += w * v2.w;
    }
    #pragma unroll
    for (int s = 0; s < Sv; s++)
        z[s] += g_esum[b * Sv + s] * (1.0f / (float)Nv);

    float* OA = bufAw(outid);
    float* OB = bufBw(outid);
    #pragma unroll
    for (int s = 0; s < Sv; s++) {
        float y = sb[s];
        #pragma unroll
        for (int t = 0; t < Sv; t++) y += z[t] * sW[s * Sv + t];
        y = (y > 0.f) ? y : 0.01f * y;
        OA[tid * Sv + s] = y;
        OB[s * BN + tid] = y;     // coalesced
    }
}

// ---------------- fused 2-layer LSTM + TPA head ----------------
__global__ void __launch_bounds__(128)
k_lstm(const float* __restrict__ Wih0, const float* __restrict__ Whh0,
       const float* __restrict__ bih0, const float* __restrict__ bhh0,
       const float* __restrict__ Wih1, const float* __restrict__ Whh1,
       const float* __restrict__ bih1, const float* __restrict__ bhh1,
       const float* __restrict__ fc1W, const float* __restrict__ fc1b,
       const float* __restrict__ fc2W, const float* __restrict__ fc2b,
       const float* __restrict__ fc3W, const float* __restrict__ fc3b,
       float* __restrict__ out, int out_size) {
    __shared__ float sWih0[100], sWhh0[100], sB0[20];
    __shared__ float sWih1[100], sWhh1[100], sB1[20];
    __shared__ float sF1[176], sF1b[16], sF2[80], sF2b[5], sF3[21], sF3b;
    int t = threadIdx.x;
    for (int i = t; i < 100; i += blockDim.x) {
        sWih0[i] = Wih0[i]; sWhh0[i] = Whh0[i];
        sWih1[i] = Wih1[i]; sWhh1[i] = Whh1[i];
    }
    for (int i = t; i < 20; i += blockDim.x) {
        sB0[i] = bih0[i] + bhh0[i];
        sB1[i] = bih1[i] + bhh1[i];
    }
    for (int i = t; i < 176; i += blockDim.x) sF1[i] = fc1W[i];
    for (int i = t; i < 80;  i += blockDim.x) sF2[i] = fc2W[i];
    for (int i = t; i < 21;  i += blockDim.x) sF3[i] = fc3W[i];
    for (int i = t; i < 16;  i += blockDim.x) sF1b[i] = fc1b[i];
    for (int i = t; i < 5;   i += blockDim.x) sF2b[i] = fc2b[i];
    if (t == 0) sF3b = fc3b[0];
    __syncthreads();

    int seq = blockIdx.x * blockDim.x + threadIdx.x;
    if (seq >= BN) return;

    float h0[Lv], c0[Lv], h1[Lv], c1l[Lv];
    #pragma unroll
    for (int l = 0; l < Lv; l++) { h0[l]=0.f; c0[l]=0.f; h1[l]=0.f; c1l[l]=0.f; }

    float h2s[Sv][Lv];

    #pragma unroll 1
    for (int tt = 0; tt < Sv; tt++) {
        float xv[Lv];
        xv[0] = g_xpB[tt * BN + seq];   // coalesced
        xv[1] = g_c1B[tt * BN + seq];
        xv[2] = g_c2B[tt * BN + seq];
        xv[3] = g_c4B[tt * BN + seq];
        xv[4] = g_c5B[tt * BN + seq];

        float z[20];
        #pragma unroll
        for (int g = 0; g < 20; g++) {
            float zz = sB0[g];
            #pragma unroll
            for (int l = 0; l < Lv; l++)
                zz += sWih0[g * Lv + l] * xv[l] + sWhh0[g * Lv + l] * h0[l];
            z[g] = zz;
        }
        #pragma unroll
        for (int l = 0; l < Lv; l++) {
            float ig = sigmf(z[l]);
            float fg = sigmf(z[5 + l]);
            float gg = tanhfast(z[10 + l]);
            float og = sigmf(z[15 + l]);
            c0[l] = fg * c0[l] + ig * gg;
            h0[l] = og * tanhfast(c0[l]);
        }
        #pragma unroll
        for (int g = 0; g < 20; g++) {
            float zz = sB1[g];
            #pragma unroll
            for (int l = 0; l < Lv; l++)
                zz += sWih1[g * Lv + l] * h0[l] + sWhh1[g * Lv + l] * h1[l];
            z[g] = zz;
        }
        #pragma unroll
        for (int l = 0; l < Lv; l++) {
            float ig = sigmf(z[l]);
            float fg = sigmf(z[5 + l]);
            float gg = tanhfast(z[10 + l]);
            float og = sigmf(z[15 + l]);
            c1l[l] = fg * c1l[l] + ig * gg;
            h1[l] = og * tanhfast(c1l[l]);
            h2s[tt][l] = h1[l];
        }
    }

    // ---- TPA head ----
    float Hc[Lv][16];
    #pragma unroll
    for (int l = 0; l < Lv; l++) {
        #pragma unroll
        for (int k = 0; k < 16; k++) {
            float acc = sF1b[k];
            #pragma unroll 1
            for (int tt = 0; tt < Sv - 1; tt++)
                acc += h2s[tt][l] * sF1[k * (Sv - 1) + tt];
            Hc[l][k] = acc;
        }
    }
    float ht[Lv];
    #pragma unroll
    for (int m = 0; m < Lv; m++) ht[m] = h2s[Sv - 1][m];

    float av[Lv];
    #pragma unroll
    for (int l = 0; l < Lv; l++) {
        float s = 0.f;
        #pragma unroll
        for (int m = 0; m < Lv; m++) {
            float hn = sF2b[m];
            #pragma unroll
            for (int k = 0; k < 16; k++) hn += Hc[l][k] * sF2[m * 16 + k];
            s += hn * ht[m];
        }
        av[l] = sigmf(s);
    }

    float y = sF3b;
    #pragma unroll
    for (int k = 0; k < 16; k++) {
        float vt = 0.f;
        #pragma unroll
        for (int l = 0; l < Lv; l++) vt += av[l] * Hc[l][k];
        y += vt * sF3[k];
    }
    #pragma unroll
    for (int m = 0; m < Lv; m++) y += ht[m] * sF3[16 + m];

    out[seq] = y;
    if (BN + seq * Lv + (Lv - 1) < out_size) {
        #pragma unroll
        for (int l = 0; l < Lv; l++)
            out[BN + seq * Lv + l] = av[l];
    }
}

// ---------------- launcher ----------------
extern "C" void kernel_launch(void* const* d_in, const int* in_sizes, int n_in,
                              void* d_out, int out_size) {
    const float* x    = (const float*)d_in[0];
    const int*   e1   = (const int*)  d_in[1];
    const int*   e2   = (const int*)  d_in[2];
    const float* g1W  = (const float*)d_in[3];
    const float* g1a  = (const float*)d_in[4];
    const float* g1lw = (const float*)d_in[5];
    const float* g1lb = (const float*)d_in[6];
    const float* g2W  = (const float*)d_in[7];
    const float* g2a  = (const float*)d_in[8];
    const float* g2lw = (const float*)d_in[9];
    const float* g2lb = (const float*)d_in[10];
    const float* gcnW = (const float*)d_in[11];
    const float* gcnb = (const float*)d_in[12];
    const float* Wih0 = (const float*)d_in[13];
    const float* Whh0 = (const float*)d_in[14];
    const float* bih0 = (const float*)d_in[15];
    const float* bhh0 = (const float*)d_in[16];
    const float* Wih1 = (const float*)d_in[17];
    const float* Whh1 = (const float*)d_in[18];
    const float* bih1 = (const float*)d_in[19];
    const float* bhh1 = (const float*)d_in[20];
    const float* fc1W = (const float*)d_in[21];
    const float* fc1b = (const float*)d_in[22];
    const float* fc2W = (const float*)d_in[23];
    const float* fc2b = (const float*)d_in[24];
    const float* fc3W = (const float*)d_in[25];
    const float* fc3b = (const float*)d_in[26];

    const int TB = 256;
    k_zero_struct<<<(Nv + TB - 1) / TB, TB>>>();
    k_transpose<<<(FSZ + TB - 1) / TB, TB>>>(x);

    k_bucket<<<(Ev + TB - 1) / TB, TB>>>(e1, 0);
    k_dedup<<<(Nv + TB - 1) / TB, TB>>>(0);
    k_rowbuild<<<(Nv + TB - 1) / TB, TB>>>(0);
    k_bucket<<<(Ev + TB - 1) / TB, TB>>>(e2, 1);
    k_dedup<<<(Nv + TB - 1) / TB, TB>>>(1);
    k_rowbuild<<<(Nv + TB - 1) / TB, TB>>>(1);

    struct StageArgs {
        int lid, xin, xout;
        const float *W, *a, *lw, *lb;
    };
    StageArgs stages[4] = {
        {0, 0, 1, g1W, g1a, g1lw, g1lb},
        {0, 1, 2, g1W, g1a, g1lw, g1lb},
        {1, 0, 3, g2W, g2a, g2lw, g2lb},
        {1, 3, 4, g2W, g2a, g2lw, g2lb},
    };
    for (int st = 0; st < 4; st++) {
        StageArgs& A = stages[st];
        k_pq<<<(Nv + TB - 1) / TB, TB>>>(A.xin, A.W, A.a);
        k_colw<<<(Nv + TB - 1) / TB, TB>>>(A.lid, A.xin, A.lw, A.lb);
        k_gathergcn<<<(BN + TB - 1) / TB, TB>>>(A.lid, A.xin, A.xout, gcnW, gcnb);
    }

    k_lstm<<<(BN + 127) / 128, 128>>>(Wih0, Whh0, bih0, bhh0,
                                      Wih1, Whh1, bih1, bhh1,
                                      fc1W, fc1b, fc2W, fc2b, fc3W, fc3b,
                                      (float*)d_out, out_size);
}

// round 4
// speedup vs baseline: 1.6876x; 1.2456x over previous
#include <cuda_runtime.h>
#include <math.h>

// Problem constants
#define Bv 4
#define Nv 8192
#define Sv 12
#define Lv 5
#define Ev 131072
#define CAP 128
#define BN (Bv*Nv)        // 32768 sequences
#define FSZ (Bv*Nv*Sv)    // floats per feature map

// ---------------- scratch ----------------
__device__ float g_xpA[FSZ], g_xpB[FSZ];
__device__ float g_c1A[FSZ], g_c1B[FSZ];
__device__ float g_c2A[FSZ], g_c2B[FSZ];
__device__ float g_c4A[FSZ], g_c4B[FSZ];
__device__ float g_c5A[FSZ], g_c5B[FSZ];

__device__ int g_fill [2][Nv];
__device__ int g_ci   [2][Nv*CAP];
__device__ int g_ucnt [2][Nv];
__device__ int g_uci  [2][Nv*CAP];
__device__ int g_mult [2][Nv*CAP];
__device__ int g_rfill[2][Nv];
__device__ int g_reid [2][Nv*CAP];

__device__ float g_p[Nv];
__device__ float g_q[Nv];
__device__ float g_w[Nv*CAP];
__device__ float g_esum[Bv*Sv];

__device__ __forceinline__ const float* bufA(int id) {
    switch (id) { case 0: return g_xpA; case 1: return g_c1A; case 2: return g_c2A;
                  case 3: return g_c4A; default: return g_c5A; }
}
__device__ __forceinline__ float* bufAw(int id) {
    switch (id) { case 0: return g_xpA; case 1: return g_c1A; case 2: return g_c2A;
                  case 3: return g_c4A; default: return g_c5A; }
}
__device__ __forceinline__ float* bufBw(int id) {
    switch (id) { case 0: return g_xpB; case 1: return g_c1B; case 2: return g_c2B;
                  case 3: return g_c4B; default: return g_c5B; }
}

__device__ __forceinline__ float sigmf(float x) { return 1.0f / (1.0f + __expf(-x)); }
__device__ __forceinline__ float tanhfast(float x) {
    return 1.0f - 2.0f / (__expf(2.0f * x) + 1.0f);
}

// ---------------- structure precompute (once per edge list) ----------------

__global__ void k_zero_struct() {
    int idx = blockIdx.x * blockDim.x + threadIdx.x;
    if (idx < Nv) {
        g_fill[0][idx] = 0; g_fill[1][idx] = 0;
        g_rfill[0][idx] = 0; g_rfill[1][idx] = 0;
    }
}

// x (B,S,N) -> A-layout (b,n,s) and B-layout (s,b,n)
__global__ void k_transpose(const float* __restrict__ x) {
    int idx = blockIdx.x * blockDim.x + threadIdx.x;
    if (idx >= FSZ) return;
    int n = idx % Nv;
    int r = idx / Nv;
    int s = r % Sv;
    int b = r / Sv;
    float v = x[idx];
    g_xpA[(b * Nv + n) * Sv + s] = v;
    g_xpB[s * BN + b * Nv + n]   = v;
}

__global__ void k_bucket(const int* __restrict__ ed, int lid) {
    int k = blockIdx.x * blockDim.x + threadIdx.x;
    if (k >= Ev) return;
    int i = ed[k];
    int j = ed[Ev + k];
    int pos = atomicAdd(&g_fill[lid][j], 1);
    if (pos < CAP) g_ci[lid][j * CAP + pos] = i;
}

// warp-per-column dedup: parallel leadership + multiplicity + ballot compaction
#define DWPB 8   // warps (columns) per block
__global__ void k_dedup(int lid) {
    __shared__ int s_ci[DWPB][CAP];
    int warp = threadIdx.x >> 5;
    int lane = threadIdx.x & 31;
    int j = blockIdx.x * DWPB + warp;
    if (j >= Nv) return;
    int k = min(g_fill[lid][j], CAP);
    const int* ci = g_ci[lid] + j * CAP;
    for (int t = lane; t < k; t += 32) s_ci[warp][t] = ci[t];
    __syncwarp();
    int* uci = g_uci[lid] + j * CAP;
    int* mlt = g_mult[lid] + j * CAP;
    int base = 0;
    for (int c = 0; c < k; c += 32) {
        int idx = c + lane;
        bool valid = idx < k;
        int i = valid ? s_ci[warp][idx] : -1;
        bool leader = valid;
        int mult = 0;
        if (valid) {
            for (int t = 0; t < idx; t++)
                if (s_ci[warp][t] == i) { leader = false; break; }
            if (leader)
                for (int t = idx; t < k; t++)
                    if (s_ci[warp][t] == i) mult++;
        }
        unsigned bal = __ballot_sync(0xFFFFFFFF, leader);
        if (leader) {
            int pos = base + __popc(bal & ((1u << lane) - 1));
            uci[pos] = i; mlt[pos] = mult;
        }
        base += __popc(bal);
    }
    if (lane == 0) g_ucnt[lid][j] = base;
}

__global__ void k_rowbuild(int lid) {
    int j = blockIdx.x * blockDim.x + threadIdx.x;
    if (j >= Nv) return;
    int u = g_ucnt[lid][j];
    const int* uci = g_uci[lid] + j * CAP;
    for (int t = 0; t < u; t++) {
        int i = uci[t];
        int pos = atomicAdd(&g_rfill[lid][i], 1);
        if (pos < CAP) g_reid[lid][i * CAP + pos] = j * CAP + t;
    }
}

// ---------------- per-stage kernels ----------------

__global__ void k_pq(int xid, const float* __restrict__ W, const float* __restrict__ a) {
    __shared__ float wa[Sv], wb[Sv];
    int t = threadIdx.x;
    if (t < Sv) {
        float s1 = 0.f, s2 = 0.f;
        #pragma unroll
        for (int u = 0; u < Sv; u++) {
            float w = W[t * Sv + u];
            s1 += w * a[u];
            s2 += w * a[Sv + u];
        }
        wa[t] = s1; wb[t] = s2;
    }
    __syncthreads();
    int i = blockIdx.x * blockDim.x + threadIdx.x;
    if (i < Bv * Sv) g_esum[i] = 0.0f;
    if (i >= Nv) return;
    const float* X0 = bufA(xid);
    float p = 0.f, q = 0.f;
    #pragma unroll
    for (int s = 0; s < Sv; s++) {
        float v = X0[i * Sv + s];
        p += v * wa[s];
        q += v * wb[s];
    }
    g_p[i] = p; g_q[i] = q;
}

__global__ void k_colw(int lid, int xid, const float* __restrict__ lw,
                       const float* __restrict__ lb) {
    int j = blockIdx.x * blockDim.x + threadIdx.x;
    if (j >= Nv) return;
    int u = g_ucnt[lid][j];
    if (u == 0) {
        const float* X = bufA(xid);
        for (int b = 0; b < Bv; b++)
            #pragma unroll
            for (int s = 0; s < Sv; s++)
                atomicAdd(&g_esum[b * Sv + s], X[(b * Nv + j) * Sv + s]);
        return;
    }
    const int* uci = g_uci[lid] + j * CAP;
    const int* mlt = g_mult[lid] + j * CAP;
    float* wv = g_w + j * CAP;
    float qj = g_q[j];
    float lwv = lw[0], lbv = lb[0];
    float m = -1e30f;
    for (int t = 0; t < u; t++) {
        float e = g_p[uci[t]] + qj;
        e = (e > 0.f) ? e : 0.2f * e;
        float val = (float)mlt[t] * (e * lwv + lbv);
        wv[t] = val;
        m = fmaxf(m, val);
    }
    float den = 0.f;
    for (int t = 0; t < u; t++) {
        float e = __expf(wv[t] - m);
        wv[t] = e;
        den += e;
    }
    float inv = 1.0f / den;
    for (int t = 0; t < u; t++) wv[t] *= inv;
}

// gather SpMM + fused GCN; no atomics
__global__ void k_gathergcn(int lid, int xid, int outid,
                            const float* __restrict__ gcnW,
                            const float* __restrict__ gcnb) {
    __shared__ float sW[Sv * Sv], sb[Sv];
    int tt = threadIdx.x;
    if (tt < Sv * Sv) sW[tt] = gcnW[tt];
    if (tt < Sv) sb[tt] = gcnb[tt];
    __syncthreads();

    int tid = blockIdx.x * blockDim.x + threadIdx.x;
    if (tid >= BN) return;
    int i = tid & (Nv - 1);
    int b = tid >> 13;

    const float* X = bufA(xid);
    const int* reid = g_reid[lid] + i * CAP;
    int deg = min(g_rfill[lid][i], CAP);

    float z[Sv];
    #pragma unroll
    for (int s = 0; s < Sv; s++) z[s] = 0.f;

    for (int t = 0; t < deg; t++) {
        int eid = reid[t];
        float w = g_w[eid];
        int j = eid >> 7;   // CAP = 128
        const float4* xr = (const float4*)(X + (b * Nv + j) * Sv);
        float4 v0 = xr[0], v1 = xr[1], v2 = xr[2];
        z[0] += w * v0.x; z[1] += w * v0.y; z[2]  += w * v0.z; z[3]  += w * v0.w;
        z[4] += w * v1.x; z[5] += w * v1.y; z[6]  += w * v1.z; z[7]  += w * v1.w;
        z[8] += w * v2.x; z[9] += w * v2.y; z[10] += w * v2.z; z[11] += w * v2.w;
    }
    #pragma unroll
    for (int s = 0; s < Sv; s++)
        z[s] += g_esum[b * Sv + s] * (1.0f / (float)Nv);

    float* OA = bufAw(outid);
    float* OB = bufBw(outid);
    #pragma unroll
    for (int s = 0; s < Sv; s++) {
        float y = sb[s];
        #pragma unroll
        for (int t = 0; t < Sv; t++) y += z[t] * sW[s * Sv + t];
        y = (y > 0.f) ? y : 0.01f * y;
        OA[tid * Sv + s] = y;
        OB[s * BN + tid] = y;
    }
}

// ---------------- fused 2-layer LSTM + TPA head ----------------
// Hc projection folded into the time loop: no h2s array, no local memory.
__global__ void __launch_bounds__(128)
k_lstm(const float* __restrict__ Wih0, const float* __restrict__ Whh0,
       const float* __restrict__ bih0, const float* __restrict__ bhh0,
       const float* __restrict__ Wih1, const float* __restrict__ Whh1,
       const float* __restrict__ bih1, const float* __restrict__ bhh1,
       const float* __restrict__ fc1W, const float* __restrict__ fc1b,
       const float* __restrict__ fc2W, const float* __restrict__ fc2b,
       const float* __restrict__ fc3W, const float* __restrict__ fc3b,
       float* __restrict__ out, int out_size) {
    __shared__ float sWih0[100], sWhh0[100], sB0[20];
    __shared__ float sWih1[100], sWhh1[100], sB1[20];
    __shared__ float sF1[176], sF1b[16], sF2[80], sF2b[5], sF3[21], sF3b;
    int t = threadIdx.x;
    for (int i = t; i < 100; i += blockDim.x) {
        sWih0[i] = Wih0[i]; sWhh0[i] = Whh0[i];
        sWih1[i] = Wih1[i]; sWhh1[i] = Whh1[i];
    }
    for (int i = t; i < 20; i += blockDim.x) {
        sB0[i] = bih0[i] + bhh0[i];
        sB1[i] = bih1[i] + bhh1[i];
    }
    for (int i = t; i < 176; i += blockDim.x) sF1[i] = fc1W[i];
    for (int i = t; i < 80;  i += blockDim.x) sF2[i] = fc2W[i];
    for (int i = t; i < 21;  i += blockDim.x) sF3[i] = fc3W[i];
    for (int i = t; i < 16;  i += blockDim.x) sF1b[i] = fc1b[i];
    for (int i = t; i < 5;   i += blockDim.x) sF2b[i] = fc2b[i];
    if (t == 0) sF3b = fc3b[0];
    __syncthreads();

    int seq = blockIdx.x * blockDim.x + threadIdx.x;
    if (seq >= BN) return;

    float h0[Lv], c0[Lv], h1[Lv], c1l[Lv];
    #pragma unroll
    for (int l = 0; l < Lv; l++) { h0[l]=0.f; c0[l]=0.f; h1[l]=0.f; c1l[l]=0.f; }

    float Hc[Lv][16];
    #pragma unroll
    for (int l = 0; l < Lv; l++)
        #pragma unroll
        for (int k = 0; k < 16; k++)
            Hc[l][k] = sF1b[k];

    #pragma unroll 1
    for (int tt = 0; tt < Sv; tt++) {
        float xv[Lv];
        xv[0] = g_xpB[tt * BN + seq];
        xv[1] = g_c1B[tt * BN + seq];
        xv[2] = g_c2B[tt * BN + seq];
        xv[3] = g_c4B[tt * BN + seq];
        xv[4] = g_c5B[tt * BN + seq];

        float z[20];
        #pragma unroll
        for (int g = 0; g < 20; g++) {
            float zz = sB0[g];
            #pragma unroll
            for (int l = 0; l < Lv; l++)
                zz += sWih0[g * Lv + l] * xv[l] + sWhh0[g * Lv + l] * h0[l];
            z[g] = zz;
        }
        #pragma unroll
        for (int l = 0; l < Lv; l++) {
            float ig = sigmf(z[l]);
            float fg = sigmf(z[5 + l]);
            float gg = tanhfast(z[10 + l]);
            float og = sigmf(z[15 + l]);
            c0[l] = fg * c0[l] + ig * gg;
            h0[l] = og * tanhfast(c0[l]);
        }
        #pragma unroll
        for (int g = 0; g < 20; g++) {
            float zz = sB1[g];
            #pragma unroll
            for (int l = 0; l < Lv; l++)
                zz += sWih1[g * Lv + l] * h0[l] + sWhh1[g * Lv + l] * h1[l];
            z[g] = zz;
        }
        #pragma unroll
        for (int l = 0; l < Lv; l++) {
            float ig = sigmf(z[l]);
            float fg = sigmf(z[5 + l]);
            float gg = tanhfast(z[10 + l]);
            float og = sigmf(z[15 + l]);
            c1l[l] = fg * c1l[l] + ig * gg;
            h1[l] = og * tanhfast(c1l[l]);
        }
        // fold fc1 projection for non-final timesteps (Hc in registers)
        if (tt < Sv - 1) {
            #pragma unroll
            for (int l = 0; l < Lv; l++) {
                float hv = h1[l];
                #pragma unroll
                for (int k = 0; k < 16; k++)
                    Hc[l][k] += hv * sF1[k * (Sv - 1) + tt];
            }
        }
    }

    float ht[Lv];
    #pragma unroll
    for (int m = 0; m < Lv; m++) ht[m] = h1[m];

    float av[Lv];
    #pragma unroll
    for (int l = 0; l < Lv; l++) {
        float s = 0.f;
        #pragma unroll
        for (int m = 0; m < Lv; m++) {
            float hn = sF2b[m];
            #pragma unroll
            for (int k = 0; k < 16; k++) hn += Hc[l][k] * sF2[m * 16 + k];
            s += hn * ht[m];
        }
        av[l] = sigmf(s);
    }

    float y = sF3b;
    #pragma unroll
    for (int k = 0; k < 16; k++) {
        float vt = 0.f;
        #pragma unroll
        for (int l = 0; l < Lv; l++) vt += av[l] * Hc[l][k];
        y += vt * sF3[k];
    }
    #pragma unroll
    for (int m = 0; m < Lv; m++) y += ht[m] * sF3[16 + m];

    out[seq] = y;
    if (BN + seq * Lv + (Lv - 1) < out_size) {
        #pragma unroll
        for (int l = 0; l < Lv; l++)
            out[BN + seq * Lv + l] = av[l];
    }
}

// ---------------- launcher ----------------
extern "C" void kernel_launch(void* const* d_in, const int* in_sizes, int n_in,
                              void* d_out, int out_size) {
    const float* x    = (const float*)d_in[0];
    const int*   e1   = (const int*)  d_in[1];
    const int*   e2   = (const int*)  d_in[2];
    const float* g1W  = (const float*)d_in[3];
    const float* g1a  = (const float*)d_in[4];
    const float* g1lw = (const float*)d_in[5];
    const float* g1lb = (const float*)d_in[6];
    const float* g2W  = (const float*)d_in[7];
    const float* g2a  = (const float*)d_in[8];
    const float* g2lw = (const float*)d_in[9];
    const float* g2lb = (const float*)d_in[10];
    const float* gcnW = (const float*)d_in[11];
    const float* gcnb = (const float*)d_in[12];
    const float* Wih0 = (const float*)d_in[13];
    const float* Whh0 = (const float*)d_in[14];
    const float* bih0 = (const float*)d_in[15];
    const float* bhh0 = (const float*)d_in[16];
    const float* Wih1 = (const float*)d_in[17];
    const float* Whh1 = (const float*)d_in[18];
    const float* bih1 = (const float*)d_in[19];
    const float* bhh1 = (const float*)d_in[20];
    const float* fc1W = (const float*)d_in[21];
    const float* fc1b = (const float*)d_in[22];
    const float* fc2W = (const float*)d_in[23];
    const float* fc2b = (const float*)d_in[24];
    const float* fc3W = (const float*)d_in[25];
    const float* fc3b = (const float*)d_in[26];

    const int TB = 256;
    k_zero_struct<<<(Nv + TB - 1) / TB, TB>>>();
    k_transpose<<<(FSZ + TB - 1) / TB, TB>>>(x);

    k_bucket<<<(Ev + TB - 1) / TB, TB>>>(e1, 0);
    k_dedup<<<Nv / DWPB, DWPB * 32>>>(0);
    k_rowbuild<<<(Nv + TB - 1) / TB, TB>>>(0);
    k_bucket<<<(Ev + TB - 1) / TB, TB>>>(e2, 1);
    k_dedup<<<Nv / DWPB, DWPB * 32>>>(1);
    k_rowbuild<<<(Nv + TB - 1) / TB, TB>>>(1);

    struct StageArgs {
        int lid, xin, xout;
        const float *W, *a, *lw, *lb;
    };
    StageArgs stages[4] = {
        {0, 0, 1, g1W, g1a, g1lw, g1lb},
        {0, 1, 2, g1W, g1a, g1lw, g1lb},
        {1, 0, 3, g2W, g2a, g2lw, g2lb},
        {1, 3, 4, g2W, g2a, g2lw, g2lb},
    };
    for (int st = 0; st < 4; st++) {
        StageArgs& A = stages[st];
        k_pq<<<(Nv + TB - 1) / TB, TB>>>(A.xin, A.W, A.a);
        k_colw<<<(Nv + TB - 1) / TB, TB>>>(A.lid, A.xin, A.lw, A.lb);
        k_gathergcn<<<(BN + TB - 1) / TB, TB>>>(A.lid, A.xin, A.xout, gcnW, gcnb);
    }

    k_lstm<<<(BN + 127) / 128, 128>>>(Wih0, Whh0, bih0, bhh0,
                                      Wih1, Whh1, bih1, bhh1,
                                      fc1W, fc1b, fc2W, fc2b, fc3W, fc3b,
                                      (float*)d_out, out_size);
}

// round 6
// speedup vs baseline: 2.6775x; 1.5866x over previous
#include <cuda_runtime.h>
#include <math.h>

// Problem constants
#define Bv 4
#define Nv 8192
#define Sv 12
#define Lv 5
#define Ev 131072
#define CAP 128
#define BN (Bv*Nv)        // 32768 sequences
#define FSZ (Bv*Nv*Sv)    // floats per feature map

// ---------------- scratch ----------------
__device__ float g_xpA[FSZ], g_xpB[FSZ];
__device__ float g_c1A[FSZ], g_c1B[FSZ];
__device__ float g_c2A[FSZ], g_c2B[FSZ];
__device__ float g_c4A[FSZ], g_c4B[FSZ];
__device__ float g_c5A[FSZ], g_c5B[FSZ];

__device__ int g_fill [2][Nv];
__device__ int g_ci   [2][Nv*CAP];
__device__ int g_ucnt [2][Nv];
__device__ int g_uci  [2][Nv*CAP];
__device__ int g_mult [2][Nv*CAP];
__device__ int g_rfill[2][Nv];
__device__ int g_reid [2][Nv*CAP];

__device__ float g_p[2][Nv];         // per paired-stage slot
__device__ float g_q[2][Nv];
__device__ float g_w[2][Nv*CAP];
__device__ float g_esum[2][Bv*Sv];

__device__ __forceinline__ const float* bufA(int id) {
    switch (id) { case 0: return g_xpA; case 1: return g_c1A; case 2: return g_c2A;
                  case 3: return g_c4A; default: return g_c5A; }
}
__device__ __forceinline__ float* bufAw(int id) {
    switch (id) { case 0: return g_xpA; case 1: return g_c1A; case 2: return g_c2A;
                  case 3: return g_c4A; default: return g_c5A; }
}
__device__ __forceinline__ float* bufBw(int id) {
    switch (id) { case 0: return g_xpB; case 1: return g_c1B; case 2: return g_c2B;
                  case 3: return g_c4B; default: return g_c5B; }
}

__device__ __forceinline__ float sigmf(float x) { return 1.0f / (1.0f + __expf(-x)); }
__device__ __forceinline__ float tanhfast(float x) {
    return 1.0f - 2.0f / (__expf(2.0f * x) + 1.0f);
}

// ---------------- transpose + struct zero ----------------
__global__ void k_transpose(const float* __restrict__ x) {
    int idx = blockIdx.x * blockDim.x + threadIdx.x;
    if (idx < Nv) {
        g_fill[0][idx] = 0; g_fill[1][idx] = 0;
        g_rfill[0][idx] = 0; g_rfill[1][idx] = 0;
    }
    if (idx >= FSZ) return;
    int n = idx % Nv;
    int r = idx / Nv;
    int s = r % Sv;
    int b = r / Sv;
    float v = x[idx];
    g_xpA[(b * Nv + n) * Sv + s] = v;
    g_xpB[s * BN + b * Nv + n]   = v;
}

// both edge lists in one launch
__global__ void k_bucket2(const int* __restrict__ e1, const int* __restrict__ e2) {
    int k = blockIdx.x * blockDim.x + threadIdx.x;
    if (k >= 2 * Ev) return;
    int lid = k >= Ev;
    int kk = k - lid * Ev;
    const int* ed = lid ? e2 : e1;
    int i = ed[kk];
    int j = ed[Ev + kk];
    int pos = atomicAdd(&g_fill[lid][j], 1);
    if (pos < CAP) g_ci[lid][j * CAP + pos] = i;
}

// warp-per-column dedup, both lists in one launch
#define DWPB 8
__global__ void k_dedup2() {
    __shared__ int s_ci[DWPB][CAP];
    int warp = threadIdx.x >> 5;
    int lane = threadIdx.x & 31;
    int jj = blockIdx.x * DWPB + warp;
    if (jj >= 2 * Nv) return;
    int lid = jj >= Nv;
    int j = jj - lid * Nv;
    int k = min(g_fill[lid][j], CAP);
    const int* ci = g_ci[lid] + j * CAP;
    for (int t = lane; t < k; t += 32) s_ci[warp][t] = ci[t];
    __syncwarp();
    int* uci = g_uci[lid] + j * CAP;
    int* mlt = g_mult[lid] + j * CAP;
    int base = 0;
    for (int c = 0; c < k; c += 32) {
        int idx = c + lane;
        bool valid = idx < k;
        int i = valid ? s_ci[warp][idx] : -1;
        bool leader = valid;
        int mult = 0;
        if (valid) {
            for (int t = 0; t < idx; t++)
                if (s_ci[warp][t] == i) { leader = false; break; }
            if (leader)
                for (int t = idx; t < k; t++)
                    if (s_ci[warp][t] == i) mult++;
        }
        unsigned bal = __ballot_sync(0xFFFFFFFF, leader);
        if (leader) {
            int pos = base + __popc(bal & ((1u << lane) - 1));
            uci[pos] = i; mlt[pos] = mult;
        }
        base += __popc(bal);
    }
    if (lane == 0) g_ucnt[lid][j] = base;
}

// fully parallel: one thread per (list, column, slot)
__global__ void k_rowbuild2() {
    int tid = blockIdx.x * blockDim.x + threadIdx.x;
    if (tid >= 2 * Nv * CAP) return;
    int lid = tid >= Nv * CAP;
    int r = tid - lid * Nv * CAP;
    int j = r >> 7;          // / CAP
    int t = r & (CAP - 1);
    if (t >= g_ucnt[lid][j]) return;
    int i = g_uci[lid][j * CAP + t];
    int pos = atomicAdd(&g_rfill[lid][i], 1);
    if (pos < CAP) g_reid[lid][i * CAP + pos] = j * CAP + t;
}

// ---------------- paired per-stage kernels ----------------
// slot 0 and slot 1 run two independent GAT stages in one launch

__global__ void k_pq2(int xidA, int xidB,
                      const float* __restrict__ WA, const float* __restrict__ aA,
                      const float* __restrict__ WB, const float* __restrict__ aB) {
    __shared__ float wa[2][Sv], wb[2][Sv];
    int t = threadIdx.x;
    if (t < Sv) {
        float s1 = 0.f, s2 = 0.f;
        #pragma unroll
        for (int u = 0; u < Sv; u++) {
            float w = WA[t * Sv + u];
            s1 += w * aA[u];
            s2 += w * aA[Sv + u];
        }
        wa[0][t] = s1; wb[0][t] = s2;
    } else if (t >= 32 && t < 32 + Sv) {
        int tt = t - 32;
        float s1 = 0.f, s2 = 0.f;
        #pragma unroll
        for (int u = 0; u < Sv; u++) {
            float w = WB[tt * Sv + u];
            s1 += w * aB[u];
            s2 += w * aB[Sv + u];
        }
        wa[1][t - 32] = s1; wb[1][t - 32] = s2;
    }
    __syncthreads();
    int i = blockIdx.x * blockDim.x + threadIdx.x;
    if (i < 2 * Bv * Sv) ((float*)g_esum)[i] = 0.0f;
    if (i >= Nv) return;
    const float* XA = bufA(xidA);
    const float* XB = bufA(xidB);
    float pA = 0.f, qA = 0.f, pB = 0.f, qB = 0.f;
    #pragma unroll
    for (int s = 0; s < Sv; s++) {
        float vA = XA[i * Sv + s];
        float vB = XB[i * Sv + s];
        pA += vA * wa[0][s]; qA += vA * wb[0][s];
        pB += vB * wa[1][s]; qB += vB * wb[1][s];
    }
    g_p[0][i] = pA; g_q[0][i] = qA;
    g_p[1][i] = pB; g_q[1][i] = qB;
}

// warp-per-column softmax; slot A uses list lidA, slot B list lidB
__global__ void k_colw2(int lidA, int lidB, int xidA, int xidB,
                        const float* __restrict__ lwA, const float* __restrict__ lbA,
                        const float* __restrict__ lwB, const float* __restrict__ lbB) {
    int warp = threadIdx.x >> 5;
    int lane = threadIdx.x & 31;
    int jj = blockIdx.x * (blockDim.x >> 5) + warp;
    if (jj >= 2 * Nv) return;
    int sid = jj >= Nv;
    int j = jj - sid * Nv;
    int lid = sid ? lidB : lidA;
    int u = g_ucnt[lid][j];
    if (u == 0) {
        const float* X = bufA(sid ? xidB : xidA);
        for (int t = lane; t < Bv * Sv; t += 32) {
            int b = t / Sv, s = t - b * Sv;
            atomicAdd(&g_esum[sid][t], X[(b * Nv + j) * Sv + s]);
        }
        return;
    }
    const int* uci = g_uci[lid] + j * CAP;
    const int* mlt = g_mult[lid] + j * CAP;
    float* wv = g_w[sid] + j * CAP;
    float qj = g_q[sid][j];
    float lwv = sid ? lwB[0] : lwA[0];
    float lbv = sid ? lbB[0] : lbA[0];
    float vals[4];
    int cnt = 0;
    float m = -1e30f;
    for (int t = lane; t < u; t += 32) {
        float e = g_p[sid][uci[t]] + qj;
        e = (e > 0.f) ? e : 0.2f * e;
        float val = (float)mlt[t] * (e * lwv + lbv);
        vals[cnt++] = val;
        m = fmaxf(m, val);
    }
    #pragma unroll
    for (int o = 16; o; o >>= 1) m = fmaxf(m, __shfl_xor_sync(0xFFFFFFFF, m, o));
    float den = 0.f;
    for (int c = 0; c < cnt; c++) {
        vals[c] = __expf(vals[c] - m);
        den += vals[c];
    }
    #pragma unroll
    for (int o = 16; o; o >>= 1) den += __shfl_xor_sync(0xFFFFFFFF, den, o);
    float inv = 1.0f / den;
    cnt = 0;
    for (int t = lane; t < u; t += 32) wv[t] = vals[cnt++] * inv;
}

// gather SpMM + fused GCN; 4 threads per (slot,b,i), shuffle reduction
__global__ void k_gather2(int lidA, int lidB, int xidA, int xidB,
                          int outA, int outB,
                          const float* __restrict__ gcnW,
                          const float* __restrict__ gcnb) {
    __shared__ float sW[Sv * Sv], sb[Sv];
    int tx = threadIdx.x;
    if (tx < Sv * Sv) sW[tx] = gcnW[tx];
    if (tx < Sv) sb[tx] = gcnb[tx];
    __syncthreads();

    int gtid = blockIdx.x * blockDim.x + threadIdx.x;
    int gid = gtid >> 2;        // (slot,b,i) id
    int sub = gtid & 3;
    if (gid >= 2 * BN) return;
    int sid = gid >= BN;
    int rem = gid - sid * BN;
    int i = rem & (Nv - 1);
    int b = rem >> 13;
    int lid = sid ? lidB : lidA;

    const float* X = bufA(sid ? xidB : xidA);
    const int* reid = g_reid[lid] + i * CAP;
    const float* wv = g_w[sid];
    int deg = min(g_rfill[lid][i], CAP);

    float z[Sv];
    #pragma unroll
    for (int s = 0; s < Sv; s++) z[s] = 0.f;

    for (int t = sub; t < deg; t += 4) {
        int eid = reid[t];
        float w = wv[eid];
        int j = eid >> 7;   // CAP = 128
        const float4* xr = (const float4*)(X + (b * Nv + j) * Sv);
        float4 v0 = xr[0], v1 = xr[1], v2 = xr[2];
        z[0] += w * v0.x; z[1] += w * v0.y; z[2]  += w * v0.z; z[3]  += w * v0.w;
        z[4] += w * v1.x; z[5] += w * v1.y; z[6]  += w * v1.z; z[7]  += w * v1.w;
        z[8] += w * v2.x; z[9] += w * v2.y; z[10] += w * v2.z; z[11] += w * v2.w;
    }
    // reduce across the 4 sub-threads (consecutive lanes)
    #pragma unroll
    for (int o = 1; o < 4; o <<= 1) {
        #pragma unroll
        for (int s = 0; s < Sv; s++)
            z[s] += __shfl_xor_sync(0xFFFFFFFF, z[s], o);
    }
    if (sub != 0) return;

    #pragma unroll
    for (int s = 0; s < Sv; s++)
        z[s] += g_esum[sid][b * Sv + s] * (1.0f / (float)Nv);

    float* OA = bufAw(sid ? outB : outA);
    float* OB = bufBw(sid ? outB : outA);
    int tid = b * Nv + i;
    #pragma unroll
    for (int s = 0; s < Sv; s++) {
        float y = sb[s];
        #pragma unroll
        for (int t = 0; t < Sv; t++) y += z[t] * sW[s * Sv + t];
        y = (y > 0.f) ? y : 0.01f * y;
        OA[tid * Sv + s] = y;
        OB[s * BN + tid] = y;
    }
}

// ---------------- fused 2-layer LSTM + TPA head ----------------
__global__ void __launch_bounds__(128)
k_lstm(const float* __restrict__ Wih0, const float* __restrict__ Whh0,
       const float* __restrict__ bih0, const float* __restrict__ bhh0,
       const float* __restrict__ Wih1, const float* __restrict__ Whh1,
       const float* __restrict__ bih1, const float* __restrict__ bhh1,
       const float* __restrict__ fc1W, const float* __restrict__ fc1b,
       const float* __restrict__ fc2W, const float* __restrict__ fc2b,
       const float* __restrict__ fc3W, const float* __restrict__ fc3b,
       float* __restrict__ out, int out_size) {
    __shared__ float sWih0[100], sWhh0[100], sB0[20];
    __shared__ float sWih1[100], sWhh1[100], sB1[20];
    __shared__ float sF1[176], sF1b[16], sF2[80], sF2b[5], sF3[21], sF3b;
    int t = threadIdx.x;
    for (int i = t; i < 100; i += blockDim.x) {
        sWih0[i] = Wih0[i]; sWhh0[i] = Whh0[i];
        sWih1[i] = Wih1[i]; sWhh1[i] = Whh1[i];
    }
    for (int i = t; i < 20; i += blockDim.x) {
        sB0[i] = bih0[i] + bhh0[i];
        sB1[i] = bih1[i] + bhh1[i];
    }
    for (int i = t; i < 176; i += blockDim.x) sF1[i] = fc1W[i];
    for (int i = t; i < 80;  i += blockDim.x) sF2[i] = fc2W[i];
    for (int i = t; i < 21;  i += blockDim.x) sF3[i] = fc3W[i];
    for (int i = t; i < 16;  i += blockDim.x) sF1b[i] = fc1b[i];
    for (int i = t; i < 5;   i += blockDim.x) sF2b[i] = fc2b[i];
    if (t == 0) sF3b = fc3b[0];
    __syncthreads();

    int seq = blockIdx.x * blockDim.x + threadIdx.x;
    if (seq >= BN) return;

    float h0[Lv], c0[Lv], h1[Lv], c1l[Lv];
    #pragma unroll
    for (int l = 0; l < Lv; l++) { h0[l]=0.f; c0[l]=0.f; h1[l]=0.f; c1l[l]=0.f; }

    float Hc[Lv][16];
    #pragma unroll
    for (int l = 0; l < Lv; l++)
        #pragma unroll
        for (int k = 0; k < 16; k++)
            Hc[l][k] = sF1b[k];

    #pragma unroll 1
    for (int tt = 0; tt < Sv; tt++) {
        float xv[Lv];
        xv[0] = g_xpB[tt * BN + seq];
        xv[1] = g_c1B[tt * BN + seq];
        xv[2] = g_c2B[tt * BN + seq];
        xv[3] = g_c4B[tt * BN + seq];
        xv[4] = g_c5B[tt * BN + seq];

        float z[20];
        #pragma unroll
        for (int g = 0; g < 20; g++) {
            float zz = sB0[g];
            #pragma unroll
            for (int l = 0; l < Lv; l++)
                zz += sWih0[g * Lv + l] * xv[l] + sWhh0[g * Lv + l] * h0[l];
            z[g] = zz;
        }
        #pragma unroll
        for (int l = 0; l < Lv; l++) {
            float ig = sigmf(z[l]);
            float fg = sigmf(z[5 + l]);
            float gg = tanhfast(z[10 + l]);
            float og = sigmf(z[15 + l]);
            c0[l] = fg * c0[l] + ig * gg;
            h0[l] = og * tanhfast(c0[l]);
        }
        #pragma unroll
        for (int g = 0; g < 20; g++) {
            float zz = sB1[g];
            #pragma unroll
            for (int l = 0; l < Lv; l++)
                zz += sWih1[g * Lv + l] * h0[l] + sWhh1[g * Lv + l] * h1[l];
            z[g] = zz;
        }
        #pragma unroll
        for (int l = 0; l < Lv; l++) {
            float ig = sigmf(z[l]);
            float fg = sigmf(z[5 + l]);
            float gg = tanhfast(z[10 + l]);
            float og = sigmf(z[15 + l]);
            c1l[l] = fg * c1l[l] + ig * gg;
            h1[l] = og * tanhfast(c1l[l]);
        }
        if (tt < Sv - 1) {
            #pragma unroll
            for (int l = 0; l < Lv; l++) {
                float hv = h1[l];
                #pragma unroll
                for (int k = 0; k < 16; k++)
                    Hc[l][k] += hv * sF1[k * (Sv - 1) + tt];
            }
        }
    }

    float ht[Lv];
    #pragma unroll
    for (int m = 0; m < Lv; m++) ht[m] = h1[m];

    float av[Lv];
    #pragma unroll
    for (int l = 0; l < Lv; l++) {
        float s = 0.f;
        #pragma unroll
        for (int m = 0; m < Lv; m++) {
            float hn = sF2b[m];
            #pragma unroll
            for (int k = 0; k < 16; k++) hn += Hc[l][k] * sF2[m * 16 + k];
            s += hn * ht[m];
        }
        av[l] = sigmf(s);
    }

    float y = sF3b;
    #pragma unroll
    for (int k = 0; k < 16; k++) {
        float vt = 0.f;
        #pragma unroll
        for (int l = 0; l < Lv; l++) vt += av[l] * Hc[l][k];
        y += vt * sF3[k];
    }
    #pragma unroll
    for (int m = 0; m < Lv; m++) y += ht[m] * sF3[16 + m];

    out[seq] = y;
    if (BN + seq * Lv + (Lv - 1) < out_size) {
        #pragma unroll
        for (int l = 0; l < Lv; l++)
            out[BN + seq * Lv + l] = av[l];
    }
}

// ---------------- launcher ----------------
extern "C" void kernel_launch(void* const* d_in, const int* in_sizes, int n_in,
                              void* d_out, int out_size) {
    const float* x    = (const float*)d_in[0];
    const int*   e1   = (const int*)  d_in[1];
    const int*   e2   = (const int*)  d_in[2];
    const float* g1W  = (const float*)d_in[3];
    const float* g1a  = (const float*)d_in[4];
    const float* g1lw = (const float*)d_in[5];
    const float* g1lb = (const float*)d_in[6];
    const float* g2W  = (const float*)d_in[7];
    const float* g2a  = (const float*)d_in[8];
    const float* g2lw = (const float*)d_in[9];
    const float* g2lb = (const float*)d_in[10];
    const float* gcnW = (const float*)d_in[11];
    const float* gcnb = (const float*)d_in[12];
    const float* Wih0 = (const float*)d_in[13];
    const float* Whh0 = (const float*)d_in[14];
    const float* bih0 = (const float*)d_in[15];
    const float* bhh0 = (const float*)d_in[16];
    const float* Wih1 = (const float*)d_in[17];
    const float* Whh1 = (const float*)d_in[18];
    const float* bih1 = (const float*)d_in[19];
    const float* bhh1 = (const float*)d_in[20];
    const float* fc1W = (const float*)d_in[21];
    const float* fc1b = (const float*)d_in[22];
    const float* fc2W = (const float*)d_in[23];
    const float* fc2b = (const float*)d_in[24];
    const float* fc3W = (const float*)d_in[25];
    const float* fc3b = (const float*)d_in[26];

    const int TB = 256;
    k_transpose<<<(FSZ + TB - 1) / TB, TB>>>(x);
    k_bucket2<<<(2 * Ev + TB - 1) / TB, TB>>>(e1, e2);
    k_dedup2<<<(2 * Nv) / DWPB, DWPB * 32>>>();
    k_rowbuild2<<<(2 * Nv * CAP) / TB, TB>>>();

    // pair A: stage0 (list0, xp -> c1) + stage2 (list1, xp -> c4)
    k_pq2<<<(Nv + TB - 1) / TB, TB>>>(0, 0, g1W, g1a, g2W, g2a);
    k_colw2<<<(2 * Nv) / 8, 256>>>(0, 1, 0, 0, g1lw, g1lb, g2lw, g2lb);
    k_gather2<<<(2 * BN * 4) / TB, TB>>>(0, 1, 0, 0, 1, 3, gcnW, gcnb);

    // pair B: stage1 (list0, c1 -> c2) + stage3 (list1, c4 -> c5)
    k_pq2<<<(Nv + TB - 1) / TB, TB>>>(1, 3, g1W, g1a, g2W, g2a);
    k_colw2<<<(2 * Nv) / 8, 256>>>(0, 1, 1, 3, g1lw, g1lb, g2lw, g2lb);
    k_gather2<<<(2 * BN * 4) / TB, TB>>>(0, 1, 1, 3, 2, 5, gcnW, gcnb);

    k_lstm<<<(BN + 127) / 128, 128>>>(Wih0, Whh0, bih0, bhh0,
                                      Wih1, Whh1, bih1, bhh1,
                                      fc1W, fc1b, fc2W, fc2b, fc3W, fc3b,
                                      (float*)d_out, out_size);
}

// round 8
// speedup vs baseline: 2.6998x; 1.0083x over previous
#include <cuda_runtime.h>
#include <math.h>

// Problem constants
#define Bv 4
#define Nv 8192
#define Sv 12
#define Lv 5
#define Ev 131072
#define CAP 128
#define BN (Bv*Nv)        // 32768 sequences
#define FSZ (Bv*Nv*Sv)    // floats per feature map

// ---------------- scratch ----------------
__device__ float g_xpA[FSZ], g_xpB[FSZ];
__device__ float g_c1A[FSZ], g_c1B[FSZ];
__device__ float g_c2A[FSZ], g_c2B[FSZ];
__device__ float g_c4A[FSZ], g_c4B[FSZ];
__device__ float g_c5A[FSZ], g_c5B[FSZ];

__device__ int g_fill [2][Nv];
__device__ int g_ci   [2][Nv*CAP];
__device__ int g_ucnt [2][Nv];
__device__ int g_uci  [2][Nv*CAP];
__device__ int g_mult [2][Nv*CAP];
__device__ int g_rfill[2][Nv];
__device__ int g_reid [2][Nv*CAP];

__device__ float g_p[2][Nv];         // per paired-stage slot
__device__ float g_q[2][Nv];
__device__ float g_w[2][Nv*CAP];
__device__ float g_esum[2][Bv*Sv];

__device__ __forceinline__ const float* bufA(int id) {
    switch (id) { case 0: return g_xpA; case 1: return g_c1A; case 2: return g_c2A;
                  case 3: return g_c4A; default: return g_c5A; }
}
__device__ __forceinline__ float* bufAw(int id) {
    switch (id) { case 0: return g_xpA; case 1: return g_c1A; case 2: return g_c2A;
                  case 3: return g_c4A; default: return g_c5A; }
}
__device__ __forceinline__ float* bufBw(int id) {
    switch (id) { case 0: return g_xpB; case 1: return g_c1B; case 2: return g_c2B;
                  case 3: return g_c4B; default: return g_c5B; }
}

// single-MUFU activations (sm_75+ tanh.approx)
__device__ __forceinline__ float tanh_ap(float x) {
    float y;
    asm("tanh.approx.f32 %0, %1;" : "=f"(y) : "f"(x));
    return y;
}
__device__ __forceinline__ float sigmf(float x) {
    return 0.5f * tanh_ap(0.5f * x) + 0.5f;
}

// ---------------- transpose + struct zero ----------------
__global__ void k_transpose(const float* __restrict__ x) {
    int idx = blockIdx.x * blockDim.x + threadIdx.x;
    if (idx < Nv) {
        g_fill[0][idx] = 0; g_fill[1][idx] = 0;
        g_rfill[0][idx] = 0; g_rfill[1][idx] = 0;
    }
    if (idx >= FSZ) return;
    int n = idx % Nv;
    int r = idx / Nv;
    int s = r % Sv;
    int b = r / Sv;
    float v = x[idx];
    g_xpA[(b * Nv + n) * Sv + s] = v;
    g_xpB[s * BN + b * Nv + n]   = v;
}

// both edge lists in one launch
__global__ void k_bucket2(const int* __restrict__ e1, const int* __restrict__ e2) {
    int k = blockIdx.x * blockDim.x + threadIdx.x;
    if (k >= 2 * Ev) return;
    int lid = k >= Ev;
    int kk = k - lid * Ev;
    const int* ed = lid ? e2 : e1;
    int i = ed[kk];
    int j = ed[Ev + kk];
    int pos = atomicAdd(&g_fill[lid][j], 1);
    if (pos < CAP) g_ci[lid][j * CAP + pos] = i;
}

// warp-per-column dedup + fused row-CSR build, both lists in one launch
#define DWPB 8
__global__ void k_dedup2() {
    __shared__ int s_ci[DWPB][CAP];
    int warp = threadIdx.x >> 5;
    int lane = threadIdx.x & 31;
    int jj = blockIdx.x * DWPB + warp;
    if (jj >= 2 * Nv) return;
    int lid = jj >= Nv;
    int j = jj - lid * Nv;
    int k = min(g_fill[lid][j], CAP);
    const int* ci = g_ci[lid] + j * CAP;
    for (int t = lane; t < k; t += 32) s_ci[warp][t] = ci[t];
    __syncwarp();
    int* uci = g_uci[lid] + j * CAP;
    int* mlt = g_mult[lid] + j * CAP;
    int base = 0;
    for (int c = 0; c < k; c += 32) {
        int idx = c + lane;
        bool valid = idx < k;
        int i = valid ? s_ci[warp][idx] : -1;
        bool leader = valid;
        int mult = 0;
        if (valid) {
            for (int t = 0; t < idx; t++)
                if (s_ci[warp][t] == i) { leader = false; break; }
            if (leader)
                for (int t = idx; t < k; t++)
                    if (s_ci[warp][t] == i) mult++;
        }
        unsigned bal = __ballot_sync(0xFFFFFFFF, leader);
        if (leader) {
            int pos = base + __popc(bal & ((1u << lane) - 1));
            uci[pos] = i; mlt[pos] = mult;
            // fused rowbuild: register this entry in source-row i's list
            int rp = atomicAdd(&g_rfill[lid][i], 1);
            if (rp < CAP) g_reid[lid][i * CAP + rp] = j * CAP + pos;
        }
        base += __popc(bal);
    }
    if (lane == 0) g_ucnt[lid][j] = base;
}

// ---------------- paired per-stage kernels ----------------
// slot 0 and slot 1 run two independent GAT stages in one launch

__global__ void k_pq2(int xidA, int xidB,
                      const float* __restrict__ WA, const float* __restrict__ aA,
                      const float* __restrict__ WB, const float* __restrict__ aB) {
    __shared__ float wa[2][Sv], wb[2][Sv];
    int t = threadIdx.x;
    if (t < Sv) {
        float s1 = 0.f, s2 = 0.f;
        #pragma unroll
        for (int u = 0; u < Sv; u++) {
            float w = WA[t * Sv + u];
            s1 += w * aA[u];
            s2 += w * aA[Sv + u];
        }
        wa[0][t] = s1; wb[0][t] = s2;
    } else if (t >= 32 && t < 32 + Sv) {
        int tt = t - 32;
        float s1 = 0.f, s2 = 0.f;
        #pragma unroll
        for (int u = 0; u < Sv; u++) {
            float w = WB[tt * Sv + u];
            s1 += w * aB[u];
            s2 += w * aB[Sv + u];
        }
        wa[1][t - 32] = s1; wb[1][t - 32] = s2;
    }
    __syncthreads();
    int i = blockIdx.x * blockDim.x + threadIdx.x;
    if (i < 2 * Bv * Sv) ((float*)g_esum)[i] = 0.0f;
    if (i >= Nv) return;
    const float* XA = bufA(xidA);
    const float* XB = bufA(xidB);
    float pA = 0.f, qA = 0.f, pB = 0.f, qB = 0.f;
    #pragma unroll
    for (int s = 0; s < Sv; s++) {
        float vA = XA[i * Sv + s];
        float vB = XB[i * Sv + s];
        pA += vA * wa[0][s]; qA += vA * wb[0][s];
        pB += vB * wa[1][s]; qB += vB * wb[1][s];
    }
    g_p[0][i] = pA; g_q[0][i] = qA;
    g_p[1][i] = pB; g_q[1][i] = qB;
}

// warp-per-column softmax; slot A uses list lidA, slot B list lidB
__global__ void k_colw2(int lidA, int lidB, int xidA, int xidB,
                        const float* __restrict__ lwA, const float* __restrict__ lbA,
                        const float* __restrict__ lwB, const float* __restrict__ lbB) {
    int warp = threadIdx.x >> 5;
    int lane = threadIdx.x & 31;
    int jj = blockIdx.x * (blockDim.x >> 5) + warp;
    if (jj >= 2 * Nv) return;
    int sid = jj >= Nv;
    int j = jj - sid * Nv;
    int lid = sid ? lidB : lidA;
    int u = g_ucnt[lid][j];
    if (u == 0) {
        const float* X = bufA(sid ? xidB : xidA);
        for (int t = lane; t < Bv * Sv; t += 32) {
            int b = t / Sv, s = t - b * Sv;
            atomicAdd(&g_esum[sid][t], X[(b * Nv + j) * Sv + s]);
        }
        return;
    }
    const int* uci = g_uci[lid] + j * CAP;
    const int* mlt = g_mult[lid] + j * CAP;
    float* wv = g_w[sid] + j * CAP;
    float qj = g_q[sid][j];
    float lwv = sid ? lwB[0] : lwA[0];
    float lbv = sid ? lbB[0] : lbA[0];
    float vals[4];
    int cnt = 0;
    float m = -1e30f;
    for (int t = lane; t < u; t += 32) {
        float e = g_p[sid][uci[t]] + qj;
        e = (e > 0.f) ? e : 0.2f * e;
        float val = (float)mlt[t] * (e * lwv + lbv);
        vals[cnt++] = val;
        m = fmaxf(m, val);
    }
    #pragma unroll
    for (int o = 16; o; o >>= 1) m = fmaxf(m, __shfl_xor_sync(0xFFFFFFFF, m, o));
    float den = 0.f;
    for (int c = 0; c < cnt; c++) {
        vals[c] = __expf(vals[c] - m);
        den += vals[c];
    }
    #pragma unroll
    for (int o = 16; o; o >>= 1) den += __shfl_xor_sync(0xFFFFFFFF, den, o);
    float inv = 1.0f / den;
    cnt = 0;
    for (int t = lane; t < u; t += 32) wv[t] = vals[cnt++] * inv;
}

// gather SpMM + fused GCN; 8 threads per (slot,b,i), shuffle reduction
#define GSUB 8
__global__ void k_gather2(int lidA, int lidB, int xidA, int xidB,
                          int outA, int outB,
                          const float* __restrict__ gcnW,
                          const float* __restrict__ gcnb) {
    __shared__ float sW[Sv * Sv], sb[Sv];
    int tx = threadIdx.x;
    if (tx < Sv * Sv) sW[tx] = gcnW[tx];
    if (tx < Sv) sb[tx] = gcnb[tx];
    __syncthreads();

    int gtid = blockIdx.x * blockDim.x + threadIdx.x;
    int gid = gtid / GSUB;      // (slot,b,i) id
    int sub = gtid % GSUB;
    if (gid >= 2 * BN) return;
    int sid = gid >= BN;
    int rem = gid - sid * BN;
    int i = rem & (Nv - 1);
    int b = rem >> 13;
    int lid = sid ? lidB : lidA;

    const float* X = bufA(sid ? xidB : xidA);
    const int* reid = g_reid[lid] + i * CAP;
    const float* wv = g_w[sid];
    int deg = min(g_rfill[lid][i], CAP);

    float z[Sv];
    #pragma unroll
    for (int s = 0; s < Sv; s++) z[s] = 0.f;

    for (int t = sub; t < deg; t += GSUB) {
        int eid = reid[t];
        float w = wv[eid];
        int j = eid >> 7;   // CAP = 128
        const float4* xr = (const float4*)(X + (b * Nv + j) * Sv);
        float4 v0 = xr[0], v1 = xr[1], v2 = xr[2];
        z[0] += w * v0.x; z[1] += w * v0.y; z[2]  += w * v0.z; z[3]  += w * v0.w;
        z[4] += w * v1.x; z[5] += w * v1.y; z[6]  += w * v1.z; z[7]  += w * v1.w;
        z[8] += w * v2.x; z[9] += w * v2.y; z[10] += w * v2.z; z[11] += w * v2.w;
    }
    // reduce across the 8 sub-threads (consecutive lanes)
    #pragma unroll
    for (int o = 1; o < GSUB; o <<= 1) {
        #pragma unroll
        for (int s = 0; s < Sv; s++)
            z[s] += __shfl_xor_sync(0xFFFFFFFF, z[s], o);
    }
    if (sub != 0) return;

    #pragma unroll
    for (int s = 0; s < Sv; s++)
        z[s] += g_esum[sid][b * Sv + s] * (1.0f / (float)Nv);

    float* OA = bufAw(sid ? outB : outA);
    float* OB = bufBw(sid ? outB : outA);
    int tid = b * Nv + i;
    #pragma unroll
    for (int s = 0; s < Sv; s++) {
        float y = sb[s];
        #pragma unroll
        for (int t = 0; t < Sv; t++) y += z[t] * sW[s * Sv + t];
        y = (y > 0.f) ? y : 0.01f * y;
        OA[tid * Sv + s] = y;
        OB[s * BN + tid] = y;
    }
}

// ---------------- fused 2-layer LSTM + TPA head ----------------
__global__ void __launch_bounds__(128)
k_lstm(const float* __restrict__ Wih0, const float* __restrict__ Whh0,
       const float* __restrict__ bih0, const float* __restrict__ bhh0,
       const float* __restrict__ Wih1, const float* __restrict__ Whh1,
       const float* __restrict__ bih1, const float* __restrict__ bhh1,
       const float* __restrict__ fc1W, const float* __restrict__ fc1b,
       const float* __restrict__ fc2W, const float* __restrict__ fc2b,
       const float* __restrict__ fc3W, const float* __restrict__ fc3b,
       float* __restrict__ out, int out_size) {
    __shared__ float sWih0[100], sWhh0[100], sB0[20];
    __shared__ float sWih1[100], sWhh1[100], sB1[20];
    __shared__ float sF1[176], sF1b[16], sF2[80], sF2b[5], sF3[21], sF3b;
    int t = threadIdx.x;
    for (int i = t; i < 100; i += blockDim.x) {
        sWih0[i] = Wih0[i]; sWhh0[i] = Whh0[i];
        sWih1[i] = Wih1[i]; sWhh1[i] = Whh1[i];
    }
    for (int i = t; i < 20; i += blockDim.x) {
        sB0[i] = bih0[i] + bhh0[i];
        sB1[i] = bih1[i] + bhh1[i];
    }
    for (int i = t; i < 176; i += blockDim.x) sF1[i] = fc1W[i];
    for (int i = t; i < 80;  i += blockDim.x) sF2[i] = fc2W[i];
    for (int i = t; i < 21;  i += blockDim.x) sF3[i] = fc3W[i];
    for (int i = t; i < 16;  i += blockDim.x) sF1b[i] = fc1b[i];
    for (int i = t; i < 5;   i += blockDim.x) sF2b[i] = fc2b[i];
    if (t == 0) sF3b = fc3b[0];
    __syncthreads();

    int seq = blockIdx.x * blockDim.x + threadIdx.x;
    if (seq >= BN) return;

    float h0[Lv], c0[Lv], h1[Lv], c1l[Lv];
    #pragma unroll
    for (int l = 0; l < Lv; l++) { h0[l]=0.f; c0[l]=0.f; h1[l]=0.f; c1l[l]=0.f; }

    float Hc[Lv][16];
    #pragma unroll
    for (int l = 0; l < Lv; l++)
        #pragma unroll
        for (int k = 0; k < 16; k++)
            Hc[l][k] = sF1b[k];

    #pragma unroll 1
    for (int tt = 0; tt < Sv; tt++) {
        float xv[Lv];
        xv[0] = g_xpB[tt * BN + seq];
        xv[1] = g_c1B[tt * BN + seq];
        xv[2] = g_c2B[tt * BN + seq];
        xv[3] = g_c4B[tt * BN + seq];
        xv[4] = g_c5B[tt * BN + seq];

        float z[20];
        #pragma unroll
        for (int g = 0; g < 20; g++) {
            float zz = sB0[g];
            #pragma unroll
            for (int l = 0; l < Lv; l++)
                zz += sWih0[g * Lv + l] * xv[l] + sWhh0[g * Lv + l] * h0[l];
            z[g] = zz;
        }
        #pragma unroll
        for (int l = 0; l < Lv; l++) {
            float ig = sigmf(z[l]);
            float fg = sigmf(z[5 + l]);
            float gg = tanh_ap(z[10 + l]);
            float og = sigmf(z[15 + l]);
            c0[l] = fg * c0[l] + ig * gg;
            h0[l] = og * tanh_ap(c0[l]);
        }
        #pragma unroll
        for (int g = 0; g < 20; g++) {
            float zz = sB1[g];
            #pragma unroll
            for (int l = 0; l < Lv; l++)
                zz += sWih1[g * Lv + l] * h0[l] + sWhh1[g * Lv + l] * h1[l];
            z[g] = zz;
        }
        #pragma unroll
        for (int l = 0; l < Lv; l++) {
            float ig = sigmf(z[l]);
            float fg = sigmf(z[5 + l]);
            float gg = tanh_ap(z[10 + l]);
            float og = sigmf(z[15 + l]);
            c1l[l] = fg * c1l[l] + ig * gg;
            h1[l] = og * tanh_ap(c1l[l]);
        }
        if (tt < Sv - 1) {
            #pragma unroll
            for (int l = 0; l < Lv; l++) {
                float hv = h1[l];
                #pragma unroll
                for (int k = 0; k < 16; k++)
                    Hc[l][k] += hv * sF1[k * (Sv - 1) + tt];
            }
        }
    }

    float ht[Lv];
    #pragma unroll
    for (int m = 0; m < Lv; m++) ht[m] = h1[m];

    float av[Lv];
    #pragma unroll
    for (int l = 0; l < Lv; l++) {
        float s = 0.f;
        #pragma unroll
        for (int m = 0; m < Lv; m++) {
            float hn = sF2b[m];
            #pragma unroll
            for (int k = 0; k < 16; k++) hn += Hc[l][k] * sF2[m * 16 + k];
            s += hn * ht[m];
        }
        av[l] = sigmf(s);
    }

    float y = sF3b;
    #pragma unroll
    for (int k = 0; k < 16; k++) {
        float vt = 0.f;
        #pragma unroll
        for (int l = 0; l < Lv; l++) vt += av[l] * Hc[l][k];
        y += vt * sF3[k];
    }
    #pragma unroll
    for (int m = 0; m < Lv; m++) y += ht[m] * sF3[16 + m];

    out[seq] = y;
    if (BN + seq * Lv + (Lv - 1) < out_size) {
        #pragma unroll
        for (int l = 0; l < Lv; l++)
            out[BN + seq * Lv + l] = av[l];
    }
}

// ---------------- launcher ----------------
extern "C" void kernel_launch(void* const* d_in, const int* in_sizes, int n_in,
                              void* d_out, int out_size) {
    const float* x    = (const float*)d_in[0];
    const int*   e1   = (const int*)  d_in[1];
    const int*   e2   = (const int*)  d_in[2];
    const float* g1W  = (const float*)d_in[3];
    const float* g1a  = (const float*)d_in[4];
    const float* g1lw = (const float*)d_in[5];
    const float* g1lb = (const float*)d_in[6];
    const float* g2W  = (const float*)d_in[7];
    const float* g2a  = (const float*)d_in[8];
    const float* g2lw = (const float*)d_in[9];
    const float* g2lb = (const float*)d_in[10];
    const float* gcnW = (const float*)d_in[11];
    const float* gcnb = (const float*)d_in[12];
    const float* Wih0 = (const float*)d_in[13];
    const float* Whh0 = (const float*)d_in[14];
    const float* bih0 = (const float*)d_in[15];
    const float* bhh0 = (const float*)d_in[16];
    const float* Wih1 = (const float*)d_in[17];
    const float* Whh1 = (const float*)d_in[18];
    const float* bih1 = (const float*)d_in[19];
    const float* bhh1 = (const float*)d_in[20];
    const float* fc1W = (const float*)d_in[21];
    const float* fc1b = (const float*)d_in[22];
    const float* fc2W = (const float*)d_in[23];
    const float* fc2b = (const float*)d_in[24];
    const float* fc3W = (const float*)d_in[25];
    const float* fc3b = (const float*)d_in[26];

    const int TB = 256;
    k_transpose<<<(FSZ + TB - 1) / TB, TB>>>(x);
    k_bucket2<<<(2 * Ev + TB - 1) / TB, TB>>>(e1, e2);
    k_dedup2<<<(2 * Nv) / DWPB, DWPB * 32>>>();

    // pair A: stage0 (list0, xp -> c1) + stage2 (list1, xp -> c4)
    k_pq2<<<(Nv + TB - 1) / TB, TB>>>(0, 0, g1W, g1a, g2W, g2a);
    k_colw2<<<(2 * Nv) / 8, 256>>>(0, 1, 0, 0, g1lw, g1lb, g2lw, g2lb);
    k_gather2<<<(2 * BN * GSUB) / TB, TB>>>(0, 1, 0, 0, 1, 3, gcnW, gcnb);

    // pair B: stage1 (list0, c1 -> c2) + stage3 (list1, c4 -> c5)
    k_pq2<<<(Nv + TB - 1) / TB, TB>>>(1, 3, g1W, g1a, g2W, g2a);
    k_colw2<<<(2 * Nv) / 8, 256>>>(0, 1, 1, 3, g1lw, g1lb, g2lw, g2lb);
    k_gather2<<<(2 * BN * GSUB) / TB, TB>>>(0, 1, 1, 3, 2, 5, gcnW, gcnb);

    k_lstm<<<(BN + 127) / 128, 128>>>(Wih0, Whh0, bih0, bhh0,
                                      Wih1, Whh1, bih1, bhh1,
                                      fc1W, fc1b, fc2W, fc2b, fc3W, fc3b,
                                      (float*)d_out, out_size);
}